// round 1
// baseline (speedup 1.0000x reference)
#include <cuda_runtime.h>
#include <cuda_bf16.h>

// Problem constants (fixed by the reference): B=4, H=12, S=2048, D=32.
#define S_LEN 2048
#define HDIM  32
#define BQ    256   // queries per CTA == threads per CTA
#define TK    64    // keys per smem tile

__global__ __launch_bounds__(BQ, 1)
void attn_tanhmax_kernel(const float* __restrict__ Q,
                         const float* __restrict__ K,
                         const float* __restrict__ V,
                         float* __restrict__ Out)
{
    // Per-tile K and V staged in shared memory as float4 rows (broadcast reads).
    __shared__ float4 sK[TK * (HDIM / 4)];   // 64 keys x 8 float4 = 8 KB
    __shared__ float4 sV[TK * (HDIM / 4)];   // 8 KB

    const int bh = blockIdx.y;                       // 0..47 (b*H+h)
    const int q  = blockIdx.x * BQ + threadIdx.x;    // query index in [0, 2048)

    const size_t head_off = (size_t)bh * S_LEN * HDIM;
    const float* Qrow = Q + head_off + (size_t)q * HDIM;
    const float* Kh   = K + head_off;
    const float* Vh   = V + head_off;

    // Load this thread's query row, pre-scaled by 1/sqrt(32).
    const float scale = 0.17677669529663687f;
    float qr[HDIM];
    #pragma unroll
    for (int i = 0; i < HDIM / 4; i++) {
        float4 t = reinterpret_cast<const float4*>(Qrow)[i];
        qr[4 * i + 0] = t.x * scale;
        qr[4 * i + 1] = t.y * scale;
        qr[4 * i + 2] = t.z * scale;
        qr[4 * i + 3] = t.w * scale;
    }

    float acc[HDIM];
    #pragma unroll
    for (int i = 0; i < HDIM; i++) acc[i] = 0.0f;
    float den = 0.0f;

    for (int t0 = 0; t0 < S_LEN; t0 += TK) {
        // Cooperative tile load: TK*8 float4 each for K and V; 256 threads -> 2 each.
        const float4* Ksrc = reinterpret_cast<const float4*>(Kh + (size_t)t0 * HDIM);
        const float4* Vsrc = reinterpret_cast<const float4*>(Vh + (size_t)t0 * HDIM);
        #pragma unroll
        for (int i = threadIdx.x; i < TK * (HDIM / 4); i += BQ) {
            sK[i] = Ksrc[i];
            sV[i] = Vsrc[i];
        }
        __syncthreads();

        #pragma unroll 4
        for (int k = 0; k < TK; k++) {
            // Dot product with 4 partial accumulators (shortens FFMA RAW chain).
            float d0 = 0.f, d1 = 0.f, d2 = 0.f, d3 = 0.f;
            #pragma unroll
            for (int i = 0; i < HDIM / 4; i++) {
                float4 kv = sK[k * (HDIM / 4) + i];
                d0 = fmaf(qr[4 * i + 0], kv.x, d0);
                d1 = fmaf(qr[4 * i + 1], kv.y, d1);
                d2 = fmaf(qr[4 * i + 2], kv.z, d2);
                d3 = fmaf(qr[4 * i + 3], kv.w, d3);
            }
            float s = (d0 + d1) + (d2 + d3);

            float ea  = __expf(s);
            float ena = __expf(-s);
            float num = ea - ena;
            den += ea + ena;

            #pragma unroll
            for (int i = 0; i < HDIM / 4; i++) {
                float4 vv = sV[k * (HDIM / 4) + i];
                acc[4 * i + 0] = fmaf(num, vv.x, acc[4 * i + 0]);
                acc[4 * i + 1] = fmaf(num, vv.y, acc[4 * i + 1]);
                acc[4 * i + 2] = fmaf(num, vv.z, acc[4 * i + 2]);
                acc[4 * i + 3] = fmaf(num, vv.w, acc[4 * i + 3]);
            }
        }
        __syncthreads();
    }

    const float inv = 1.0f / den;
    float* Orow = Out + head_off + (size_t)q * HDIM;
    #pragma unroll
    for (int i = 0; i < HDIM / 4; i++) {
        float4 o;
        o.x = acc[4 * i + 0] * inv;
        o.y = acc[4 * i + 1] * inv;
        o.z = acc[4 * i + 2] * inv;
        o.w = acc[4 * i + 3] * inv;
        reinterpret_cast<float4*>(Orow)[i] = o;
    }
}

extern "C" void kernel_launch(void* const* d_in, const int* in_sizes, int n_in,
                              void* d_out, int out_size)
{
    const float* Q = (const float*)d_in[0];
    const float* K = (const float*)d_in[1];
    const float* V = (const float*)d_in[2];
    // d_in[3] = attn_mask — dead in the reference (masked_fill result discarded).
    float* Out = (float*)d_out;

    const int BH = 4 * 12;                 // B*H = 48
    dim3 grid(S_LEN / BQ, BH);             // (8, 48) = 384 CTAs
    attn_tanhmax_kernel<<<grid, BQ>>>(Q, K, V, Out);
}

// round 2
// speedup vs baseline: 1.2738x; 1.2738x over previous
#include <cuda_runtime.h>
#include <cuda_bf16.h>

// B=4, H=12, S=2048, D=32 fixed.
#define S_LEN 2048
#define HDIM  32
#define NTHR  128   // threads per CTA
#define QPT   2     // queries per thread
#define BQ    (NTHR * QPT)   // 256 queries per CTA
#define TK    64    // keys per smem tile

typedef unsigned long long u64;

#define FMA2(d, a, b, c) asm("fma.rn.f32x2 %0, %1, %2, %3;" : "=l"(d) : "l"(a), "l"(b), "l"(c))
#define MUL2(d, a, b)    asm("mul.rn.f32x2 %0, %1, %2;"     : "=l"(d) : "l"(a), "l"(b))
#define ADD2(d, a, b)    asm("add.rn.f32x2 %0, %1, %2;"     : "=l"(d) : "l"(a), "l"(b))
#define PACK2(d, x, y)   asm("mov.b64 %0, {%1, %2};"        : "=l"(d) : "f"(x), "f"(y))
#define UNPACK2(x, y, d) asm("mov.b64 {%0, %1}, %2;"        : "=f"(x), "=f"(y) : "l"(d))

__global__ __launch_bounds__(NTHR, 1)
void attn_tanhmax_f32x2_kernel(const float* __restrict__ Q,
                               const float* __restrict__ K,
                               const float* __restrict__ V,
                               float* __restrict__ Out)
{
    // K/V tiles staged as 16B vectors; rows are 128B (8 x ulonglong2).
    __shared__ ulonglong2 sK[TK * 8];   // 8 KB
    __shared__ ulonglong2 sV[TK * 8];   // 8 KB

    const int bh = blockIdx.y;                    // b*H + h, 0..47
    const int qa = blockIdx.x * BQ + threadIdx.x;         // query A
    const int qb = qa + NTHR;                             // query B

    const size_t head_off = (size_t)bh * S_LEN * HDIM;
    const float* Kh = K + head_off;
    const float* Vh = V + head_off;

    // Load both query rows as packed f32x2, pre-scaled by 1/sqrt(32).
    const float scale = 0.17677669529663687f;
    u64 scale2; PACK2(scale2, scale, scale);

    u64 q2a[16], q2b[16];
    {
        const ulonglong2* Qa = reinterpret_cast<const ulonglong2*>(Q + head_off + (size_t)qa * HDIM);
        const ulonglong2* Qb = reinterpret_cast<const ulonglong2*>(Q + head_off + (size_t)qb * HDIM);
        #pragma unroll
        for (int i = 0; i < 8; i++) {
            ulonglong2 ta = Qa[i];
            ulonglong2 tb = Qb[i];
            MUL2(q2a[2 * i + 0], ta.x, scale2);
            MUL2(q2a[2 * i + 1], ta.y, scale2);
            MUL2(q2b[2 * i + 0], tb.x, scale2);
            MUL2(q2b[2 * i + 1], tb.y, scale2);
        }
    }

    u64 acca[16], accb[16];
    #pragma unroll
    for (int i = 0; i < 16; i++) { acca[i] = 0ull; accb[i] = 0ull; }
    float dena = 0.0f, denb = 0.0f;

    for (int t0 = 0; t0 < S_LEN; t0 += TK) {
        // Cooperative tile load: TK*8 = 512 vec16 each; 128 threads -> 4 each per array.
        const ulonglong2* Ksrc = reinterpret_cast<const ulonglong2*>(Kh + (size_t)t0 * HDIM);
        const ulonglong2* Vsrc = reinterpret_cast<const ulonglong2*>(Vh + (size_t)t0 * HDIM);
        #pragma unroll
        for (int i = threadIdx.x; i < TK * 8; i += NTHR) {
            sK[i] = Ksrc[i];
            sV[i] = Vsrc[i];
        }
        __syncthreads();

        #pragma unroll 2
        for (int k = 0; k < TK; k++) {
            const ulonglong2* kr = &sK[k * 8];

            // Dot products for both queries, 2 packed accumulators each.
            u64 da0 = 0ull, da1 = 0ull, db0 = 0ull, db1 = 0ull;
            #pragma unroll
            for (int i = 0; i < 8; i++) {
                ulonglong2 kk = kr[i];
                FMA2(da0, q2a[2 * i + 0], kk.x, da0);
                FMA2(da1, q2a[2 * i + 1], kk.y, da1);
                FMA2(db0, q2b[2 * i + 0], kk.x, db0);
                FMA2(db1, q2b[2 * i + 1], kk.y, db1);
            }
            u64 ra, rb;
            ADD2(ra, da0, da1);
            ADD2(rb, db0, db1);
            float alo, ahi, blo, bhi;
            UNPACK2(alo, ahi, ra);
            UNPACK2(blo, bhi, rb);
            float sa = alo + ahi;
            float sb = blo + bhi;

            float eaa = __expf(sa), ena = __expf(-sa);
            float eab = __expf(sb), enb = __expf(-sb);
            float numa = eaa - ena;  dena += eaa; dena += ena;
            float numb = eab - enb;  denb += eab; denb += enb;
            u64 numa2, numb2;
            PACK2(numa2, numa, numa);
            PACK2(numb2, numb, numb);

            const ulonglong2* vr = &sV[k * 8];
            #pragma unroll
            for (int i = 0; i < 8; i++) {
                ulonglong2 vv = vr[i];
                FMA2(acca[2 * i + 0], numa2, vv.x, acca[2 * i + 0]);
                FMA2(acca[2 * i + 1], numa2, vv.y, acca[2 * i + 1]);
                FMA2(accb[2 * i + 0], numb2, vv.x, accb[2 * i + 0]);
                FMA2(accb[2 * i + 1], numb2, vv.y, accb[2 * i + 1]);
            }
        }
        __syncthreads();
    }

    // Epilogue: normalize and store both query rows.
    const float inva = 1.0f / dena;
    const float invb = 1.0f / denb;
    u64 inva2, invb2;
    PACK2(inva2, inva, inva);
    PACK2(invb2, invb, invb);

    ulonglong2* Oa = reinterpret_cast<ulonglong2*>(Out + head_off + (size_t)qa * HDIM);
    ulonglong2* Ob = reinterpret_cast<ulonglong2*>(Out + head_off + (size_t)qb * HDIM);
    #pragma unroll
    for (int i = 0; i < 8; i++) {
        ulonglong2 oa, ob;
        MUL2(oa.x, acca[2 * i + 0], inva2);
        MUL2(oa.y, acca[2 * i + 1], inva2);
        MUL2(ob.x, accb[2 * i + 0], invb2);
        MUL2(ob.y, accb[2 * i + 1], invb2);
        Oa[i] = oa;
        Ob[i] = ob;
    }
}

extern "C" void kernel_launch(void* const* d_in, const int* in_sizes, int n_in,
                              void* d_out, int out_size)
{
    const float* Q = (const float*)d_in[0];
    const float* K = (const float*)d_in[1];
    const float* V = (const float*)d_in[2];
    // d_in[3] = attn_mask — dead in the reference (masked_fill result discarded).
    float* Out = (float*)d_out;

    const int BH = 4 * 12;              // 48 heads
    dim3 grid(S_LEN / BQ, BH);          // (8, 48) = 384 CTAs
    attn_tanhmax_f32x2_kernel<<<grid, NTHR>>>(Q, K, V, Out);
}

// round 4
// speedup vs baseline: 2.5226x; 1.9804x over previous
#include <cuda_runtime.h>
#include <cuda_bf16.h>
#include <cstdint>

// B=4, H=12, S=2048, D=32 fixed.
#define S_LEN   2048
#define HDIM    32
#define TQ      128          // queries per CTA (8 warps x 16 rows)
#define TN      64           // keys per tile
#define NTILES  (S_LEN / TN)
#define NTHR    256

// smem word (b32) strides, padded for bank-conflict-free fragment reads
#define KSTRIDE 20           // K row: 16 data words (32 bf16) + 4 pad
#define VSTRIDE 36           // V^T row: 32 data words (64 bf16) + 4 pad

__device__ __forceinline__ void mma16816(float* c, const unsigned* a, unsigned b0, unsigned b1) {
    asm volatile(
        "mma.sync.aligned.m16n8k16.row.col.f32.bf16.bf16.f32 "
        "{%0,%1,%2,%3}, {%4,%5,%6,%7}, {%8,%9}, {%0,%1,%2,%3};"
        : "+f"(c[0]), "+f"(c[1]), "+f"(c[2]), "+f"(c[3])
        : "r"(a[0]), "r"(a[1]), "r"(a[2]), "r"(a[3]), "r"(b0), "r"(b1));
}

__device__ __forceinline__ unsigned bpack(__nv_bfloat16 lo, __nv_bfloat16 hi) {
    return (unsigned)__bfloat16_as_ushort(lo) | ((unsigned)__bfloat16_as_ushort(hi) << 16);
}
// split (a,b) into bf16x2 hi (leading bits) and lo (residual)
__device__ __forceinline__ void split2(float a, float b, unsigned& hi, unsigned& lo) {
    __nv_bfloat16 ah = __float2bfloat16_rn(a), bh = __float2bfloat16_rn(b);
    __nv_bfloat16 al = __float2bfloat16_rn(a - __bfloat162float(ah));
    __nv_bfloat16 bl = __float2bfloat16_rn(b - __bfloat162float(bh));
    hi = bpack(ah, bh);
    lo = bpack(al, bl);
}

__global__ __launch_bounds__(NTHR, 2)
void attn_hmma_kernel(const float* __restrict__ Q,
                      const float* __restrict__ K,
                      const float* __restrict__ V,
                      float* __restrict__ Out)
{
    __shared__ unsigned sKhi[TN * KSTRIDE];      // 5120 B
    __shared__ unsigned sKlo[TN * KSTRIDE];      // 5120 B
    __shared__ unsigned sVhi[HDIM * VSTRIDE];    // 4608 B
    __shared__ unsigned sVlo[HDIM * VSTRIDE];    // 4608 B

    const int tid  = threadIdx.x;
    const int wid  = tid >> 5;
    const int lane = tid & 31;
    const int qr   = lane >> 2;       // quad row 0..7
    const int qc   = lane & 3;        // quad col 0..3

    const int bh = blockIdx.y;
    const size_t head_off = (size_t)bh * S_LEN * HDIM;
    const float* Kh = K + head_off;
    const float* Vh = V + head_off;

    // ---- Q fragments (persistent, scaled by 1/sqrt(32), bf16 hi/lo split) ----
    // A-frag m16n8k16: reg r = rw + 2*kh holds (row=qr+8*rw, d = kc*16 + kh*8 + qc*2, +1)
    unsigned qhi[2][4], qlo[2][4];
    {
        const float sc = 0.17677669529663687f;
        const float* Qb = Q + head_off + ((size_t)blockIdx.x * TQ + wid * 16) * HDIM;
        #pragma unroll
        for (int kc = 0; kc < 2; kc++)
            #pragma unroll
            for (int kh = 0; kh < 2; kh++)
                #pragma unroll
                for (int rw = 0; rw < 2; rw++) {
                    const float2 v = *(const float2*)(Qb + (qr + 8 * rw) * HDIM
                                                      + kc * 16 + kh * 8 + qc * 2);
                    split2(v.x * sc, v.y * sc, qhi[kc][rw + 2 * kh], qlo[kc][rw + 2 * kh]);
                }
    }

    // ---- persistent accumulators ----
    float ctx[4][4];                 // context: nb2 (d-block) x c-frag
    #pragma unroll
    for (int i = 0; i < 4; i++)
        #pragma unroll
        for (int j = 0; j < 4; j++) ctx[i][j] = 0.0f;
    float den0 = 0.0f, den1 = 0.0f;  // rows qr, qr+8 partial denominators

    // ---- tile-0 global prefetch ----
    // K: 512 float4 per tile, 2 per thread. V: per-warp transpose gather, 8 floats.
    float4 pk0, pk1;
    float  pv[8];
    {
        const float4* Ks = (const float4*)Kh;
        pk0 = Ks[tid];
        pk1 = Ks[tid + NTHR];
        const float* Vt = Vh + (size_t)(wid * 8) * HDIM + lane;
        #pragma unroll
        for (int i = 0; i < 8; i++) pv[i] = Vt[i * HDIM];
    }

    for (int t = 0; t < NTILES; t++) {
        // ---- stage prefetched tile into smem ----
        {
            int idx = tid;                       // K element 0
            int key = idx >> 3, d4 = idx & 7;
            unsigned h0, l0, h1, l1;
            split2(pk0.x, pk0.y, h0, l0);
            split2(pk0.z, pk0.w, h1, l1);
            sKhi[key * KSTRIDE + d4 * 2] = h0; sKhi[key * KSTRIDE + d4 * 2 + 1] = h1;
            sKlo[key * KSTRIDE + d4 * 2] = l0; sKlo[key * KSTRIDE + d4 * 2 + 1] = l1;
            idx = tid + NTHR;                    // K element 1
            key = idx >> 3; d4 = idx & 7;
            split2(pk1.x, pk1.y, h0, l0);
            split2(pk1.z, pk1.w, h1, l1);
            sKhi[key * KSTRIDE + d4 * 2] = h0; sKhi[key * KSTRIDE + d4 * 2 + 1] = h1;
            sKlo[key * KSTRIDE + d4 * 2] = l0; sKlo[key * KSTRIDE + d4 * 2 + 1] = l1;

            // V^T: lane = d row, warp covers keys 8*wid..8*wid+7 -> words 4*wid..+3
            unsigned vh[4], vl[4];
            #pragma unroll
            for (int i = 0; i < 4; i++) split2(pv[2 * i], pv[2 * i + 1], vh[i], vl[i]);
            unsigned wo = lane * VSTRIDE + wid * 4;
            #pragma unroll
            for (int i = 0; i < 4; i++) { sVhi[wo + i] = vh[i]; sVlo[wo + i] = vl[i]; }
        }
        __syncthreads();

        // ---- prefetch next tile ----
        if (t + 1 < NTILES) {
            const float4* Ks = (const float4*)(Kh + (size_t)(t + 1) * TN * HDIM);
            pk0 = Ks[tid];
            pk1 = Ks[tid + NTHR];
            const float* Vt = Vh + (size_t)((t + 1) * TN + wid * 8) * HDIM + lane;
            #pragma unroll
            for (int i = 0; i < 8; i++) pv[i] = Vt[i * HDIM];
        }

        // ---- QK^T: scores in C-frags cf[nb][4] ----
        float cf[8][4];
        #pragma unroll
        for (int nb = 0; nb < 8; nb++) {
            #pragma unroll
            for (int j = 0; j < 4; j++) cf[nb][j] = 0.0f;
            const unsigned kw = (nb * 8 + qr) * KSTRIDE + qc;
            #pragma unroll
            for (int kc = 0; kc < 2; kc++) {
                unsigned bh0 = sKhi[kw + kc * 8], bh1 = sKhi[kw + kc * 8 + 4];
                unsigned bl0 = sKlo[kw + kc * 8], bl1 = sKlo[kw + kc * 8 + 4];
                mma16816(cf[nb], qhi[kc], bh0, bh1);
                mma16816(cf[nb], qhi[kc], bl0, bl1);
                mma16816(cf[nb], qlo[kc], bh0, bh1);
            }
        }

        // ---- convert: num = e^s - e^-s (bf16 hi/lo A-frags), den += e^s + e^-s ----
        unsigned phi[4][4], plo[4][4];
        #pragma unroll
        for (int nb = 0; nb < 8; nb++) {
            float e0 = __expf(cf[nb][0]), f0 = __expf(-cf[nb][0]);
            float e1 = __expf(cf[nb][1]), f1 = __expf(-cf[nb][1]);
            float e2 = __expf(cf[nb][2]), f2 = __expf(-cf[nb][2]);
            float e3 = __expf(cf[nb][3]), f3 = __expf(-cf[nb][3]);
            den0 += (e0 + f0) + (e1 + f1);
            den1 += (e2 + f2) + (e3 + f3);
            cf[nb][0] = e0 - f0; cf[nb][1] = e1 - f1;
            cf[nb][2] = e2 - f2; cf[nb][3] = e3 - f3;
        }
        #pragma unroll
        for (int j = 0; j < 4; j++) {
            split2(cf[2 * j][0],     cf[2 * j][1],     phi[j][0], plo[j][0]);
            split2(cf[2 * j][2],     cf[2 * j][3],     phi[j][1], plo[j][1]);
            split2(cf[2 * j + 1][0], cf[2 * j + 1][1], phi[j][2], plo[j][2]);
            split2(cf[2 * j + 1][2], cf[2 * j + 1][3], phi[j][3], plo[j][3]);
        }

        // ---- P @ V: ctx += Phi@Vhi + Phi@Vlo + Plo@Vhi ----
        #pragma unroll
        for (int nb2 = 0; nb2 < 4; nb2++) {
            const unsigned vwbase = (nb2 * 8 + qr) * VSTRIDE + qc;
            #pragma unroll
            for (int kc2 = 0; kc2 < 4; kc2++) {
                unsigned vw = vwbase + kc2 * 8;
                unsigned bh0 = sVhi[vw], bh1 = sVhi[vw + 4];
                unsigned bl0 = sVlo[vw], bl1 = sVlo[vw + 4];
                mma16816(ctx[nb2], phi[kc2], bh0, bh1);
                mma16816(ctx[nb2], phi[kc2], bl0, bl1);
                mma16816(ctx[nb2], plo[kc2], bh0, bh1);
            }
        }
        __syncthreads();
    }

    // ---- epilogue: reduce den across the quad, normalize, store ----
    den0 += __shfl_xor_sync(0xFFFFFFFFu, den0, 1);
    den0 += __shfl_xor_sync(0xFFFFFFFFu, den0, 2);
    den1 += __shfl_xor_sync(0xFFFFFFFFu, den1, 1);
    den1 += __shfl_xor_sync(0xFFFFFFFFu, den1, 2);
    const float inv0 = 1.0f / den0;
    const float inv1 = 1.0f / den1;

    float* Ob = Out + head_off + ((size_t)blockIdx.x * TQ + wid * 16) * HDIM;
    #pragma unroll
    for (int nb2 = 0; nb2 < 4; nb2++) {
        const int d0 = nb2 * 8 + qc * 2;
        *(float2*)(Ob + qr * HDIM + d0)       = make_float2(ctx[nb2][0] * inv0, ctx[nb2][1] * inv0);
        *(float2*)(Ob + (qr + 8) * HDIM + d0) = make_float2(ctx[nb2][2] * inv1, ctx[nb2][3] * inv1);
    }
}

extern "C" void kernel_launch(void* const* d_in, const int* in_sizes, int n_in,
                              void* d_out, int out_size)
{
    const float* Q = (const float*)d_in[0];
    const float* K = (const float*)d_in[1];
    const float* V = (const float*)d_in[2];
    // d_in[3] = attn_mask — dead in the reference.
    float* Out = (float*)d_out;

    dim3 grid(S_LEN / TQ, 4 * 12);   // (16, 48) = 768 CTAs
    attn_hmma_kernel<<<grid, NTHR>>>(Q, K, V, Out);
}